// round 17
// baseline (speedup 1.0000x reference)
#include <cuda_runtime.h>
#include <cuda_bf16.h>

#define BATCH    4
#define NBOX     8192
#define TILE     128
#define THREADS  256
#define T_TILES  (NBOX / TILE)                  // 64
#define NPAIRS   (T_TILES * (T_TILES + 1) / 2)  // 2080
#define NBINS    128

#define CINV (-0.34657359027997264f)   // 1/C = -ln2/2 ; C = -2/ln2

// Scratch (no device allocs).
__device__ float  g_part2[T_TILES][BATCH * NBOX];   // 8 MB
__device__ float  g_stage[8][BATCH * NBOX];         // 1 MB
__device__ float  g_adj[BATCH * NBOX];              // 128 KB
__device__ float4 g_sbox[BATCH * NBOX];             // bucketed boxes
__device__ float  g_sscore[BATCH * NBOX];           // bucketed scores
__device__ float2 g_tmeta[BATCH][T_TILES];          // exact (min_x1, max_x2) per tile
__device__ float  g_S[BATCH];                       // per-batch score sum
__device__ float  g_pmax[32];

// ---------------------------------------------------------------------------
// Kernel 0: deterministic counting-sort partition by x1 (identical to R16).
// ---------------------------------------------------------------------------
__global__ __launch_bounds__(1024)
void bucket_kernel(const float* __restrict__ boxes,
                   const float* __restrict__ scores)
{
    const int b   = blockIdx.x;
    const int tid = threadIdx.x;
    const int w   = tid >> 5;
    const int l   = tid & 31;

    __shared__ int   hist[NBINS][33];
    __shared__ int   woff[NBINS][33];
    __shared__ int   binBase[NBINS];
    __shared__ int   smaxi[T_TILES];
    __shared__ int   smini[T_TILES];
    __shared__ float ssum[32];

    const float4* __restrict__ box4 = reinterpret_cast<const float4*>(boxes) + (size_t)b * NBOX;
    const float*  __restrict__ sc   = scores + (size_t)b * NBOX;

    for (int i = tid; i < NBINS * 33; i += 1024) (&hist[0][0])[i] = 0;
    if (tid < T_TILES) { smaxi[tid] = 0; smini[tid] = 0x7fffffff; }
    __syncthreads();

    int mybin[8];
    #pragma unroll
    for (int k = 0; k < 8; ++k) {
        int idx = w * 256 + k * 32 + l;
        float x1 = box4[idx].x;
        int bin = (int)(x1 * (NBINS / 200.0f));
        bin = bin < 0 ? 0 : (bin > NBINS - 1 ? NBINS - 1 : bin);
        mybin[k] = bin;
        unsigned mask = __match_any_sync(0xffffffffu, bin);
        if (l == __ffs(mask) - 1) hist[bin][w] += __popc(mask);
        __syncwarp();
    }
    __syncthreads();

    if (tid < NBINS) {
        int s = 0;
        #pragma unroll 1
        for (int ww = 0; ww < 32; ++ww) s += hist[tid][ww];
        binBase[tid] = s;
    }
    __syncthreads();
    if (tid == 0) {
        int acc = 0;
        #pragma unroll 1
        for (int bin = 0; bin < NBINS; ++bin) {
            int t = binBase[bin]; binBase[bin] = acc; acc += t;
        }
    }
    __syncthreads();
    if (tid < NBINS) {
        int acc = binBase[tid];
        #pragma unroll 1
        for (int ww = 0; ww < 32; ++ww) { woff[tid][ww] = acc; acc += hist[tid][ww]; }
    }
    __syncthreads();
    for (int i = tid; i < NBINS * 33; i += 1024) (&hist[0][0])[i] = 0;
    __syncthreads();

    float4* __restrict__ dstB = g_sbox   + (size_t)b * NBOX;
    float*  __restrict__ dstS = g_sscore + (size_t)b * NBOX;

    float mysum = 0.0f;
    #pragma unroll
    for (int k = 0; k < 8; ++k) {
        int idx = w * 256 + k * 32 + l;
        int bin = mybin[k];
        unsigned mask  = __match_any_sync(0xffffffffu, bin);
        int      myoff = __popc(mask & ((1u << l) - 1u));
        int      base  = hist[bin][w];
        __syncwarp();
        if (l == __ffs(mask) - 1) hist[bin][w] = base + __popc(mask);
        __syncwarp();
        int pos = woff[bin][w] + base + myoff;

        float4 v = box4[idx];
        float  s = sc[idx];
        dstB[pos] = v;
        dstS[pos] = s;
        mysum += s;

        int t = pos >> 7;
        atomicMax(&smaxi[t], __float_as_int(v.z));
        atomicMin(&smini[t], __float_as_int(v.x));
    }
    __syncthreads();
    if (tid < T_TILES)
        g_tmeta[b][tid] = make_float2(__int_as_float(smini[tid]),
                                      __int_as_float(smaxi[tid]));

    #pragma unroll
    for (int o = 16; o; o >>= 1) mysum += __shfl_xor_sync(0xffffffffu, mysum, o);
    if (l == 0) ssum[w] = mysum;
    __syncthreads();
    if (tid == 0) {
        float S = ssum[0];
        #pragma unroll
        for (int ww = 1; ww < 32; ++ww) S = __fadd_rn(S, ssum[ww]);
        g_S[b] = S;
    }
}

// ---------------------------------------------------------------------------
// Kernel 1: symmetric tile-pair kernel with ROW COMPACTION.
// Columns (8/thread, cg*8+c) live in registers; active rows are streamed
// from shared over a deterministically compacted list (ballot+popc order).
// Entries only computed for rows that can overlap tj in x.
// ---------------------------------------------------------------------------
__global__ __launch_bounds__(THREADS, 2)
void symm_kernel()
{
    const int b = blockIdx.y;

    // triangular decode: pair index -> (ti, tj), ti <= tj
    const int p = blockIdx.x;
    int ti = (int)((2.0f * T_TILES + 1.0f
                    - sqrtf((2.0f * T_TILES + 1.0f) * (2.0f * T_TILES + 1.0f) - 8.0f * p)) * 0.5f);
    ti = ti < 0 ? 0 : (ti >= T_TILES ? T_TILES - 1 : ti);
    #pragma unroll 1
    while (ti > 0 && (ti * (2 * T_TILES - ti + 1)) / 2 > p) --ti;
    #pragma unroll 1
    while (((ti + 1) * (2 * T_TILES - ti)) / 2 <= p) ++ti;
    const int tj = ti + (p - (ti * (2 * T_TILES - ti + 1)) / 2);
    const bool diag = (ti == tj);

    const int tid   = threadIdx.x;
    const int ibase = ti * TILE;
    const int jbase = tj * TILE;

    float* __restrict__ prow = &g_part2[tj][(size_t)b * NBOX];
    float* __restrict__ pcol = &g_part2[ti][(size_t)b * NBOX];

    // ---- exact tile-level cull ----
    {
        float2 mi = g_tmeta[b][ti];
        float2 mj = g_tmeta[b][tj];
        if (mj.x >= mi.y) {
            if (tid < TILE) {
                prow[ibase + tid] = 0.0f;
                pcol[jbase + tid] = 0.0f;
            }
            return;
        }
    }

    __shared__ float4 sboxI[TILE];
    __shared__ float2 sasI[TILE];     // (area*CINV, score)
    __shared__ float4 sboxJ[TILE];
    __shared__ float2 sasJ[TILE];
    __shared__ float  red[TILE * 17];
    __shared__ int    cRow[TILE];
    __shared__ int    wcnt[8], woff2[8];
    __shared__ int    s_nR;

    const int rg = tid >> 4;   // 0..15 row-stream lane
    const int cg = tid & 15;   // 0..15 column group

    // stage both tiles (area pre-scaled by CINV)
    if (tid < TILE) {
        float4 v = g_sbox[(size_t)b * NBOX + ibase + tid];
        sboxI[tid] = v;
        sasI[tid]  = make_float2((v.z - v.x) * (v.w - v.y) * CINV,
                                 g_sscore[(size_t)b * NBOX + ibase + tid]);
    } else {
        int k = tid - TILE;
        float4 v = g_sbox[(size_t)b * NBOX + jbase + k];
        sboxJ[k] = v;
        sasJ[k]  = make_float2((v.z - v.x) * (v.w - v.y) * CINV,
                               g_sscore[(size_t)b * NBOX + jbase + k]);
    }
    // zero row-partial buffer
    for (int i = tid; i < TILE * 17; i += THREADS) red[i] = 0.0f;
    __syncthreads();

    // ---- deterministic row compaction (rows of ti vs tj's x-range) ----
    int pred = 0;
    if (tid < TILE) {
        float2 mj = g_tmeta[b][tj];
        float  x1 = sboxI[tid].x;
        float  x2 = sboxI[tid].z;
        pred = (x2 > mj.x) && (x1 < mj.y);
    }
    unsigned bal = __ballot_sync(0xffffffffu, pred);
    if ((tid & 31) == 0) wcnt[tid >> 5] = __popc(bal);
    __syncthreads();
    if (tid == 0) {
        int acc = 0;
        #pragma unroll
        for (int w = 0; w < 8; ++w) { woff2[w] = acc; acc += wcnt[w]; }
        s_nR = acc;
    }
    __syncthreads();
    if (pred) {
        int pos = woff2[tid >> 5] + __popc(bal & ((1u << (tid & 31)) - 1u));
        cRow[pos] = tid;
    }
    __syncthreads();
    const int nR = s_nR;

    // ---- load this thread's 8 columns into registers ----
    float jx1[8], jy1[8], jx2[8], jy2[8], jaC[8], js[8];
    #pragma unroll
    for (int c = 0; c < 8; ++c) {
        int jc = cg * 8 + c;
        float4 v = sboxJ[jc];
        float2 a = sasJ[jc];
        jx1[c] = v.x; jy1[c] = v.y; jx2[c] = v.z; jy2[c] = v.w;
        jaC[c] = a.x; js[c] = a.y;
    }

    // ---- streamed row loop over compacted active rows ----
    float cacc[8] = {0,0,0,0,0,0,0,0};

    #pragma unroll 1
    for (int k = rg; k < nR; k += 16) {
        const int   ir  = cRow[k];
        const float4 rb = sboxI[ir];
        const float2 ra = sasI[ir];   // (area_i*CINV, s_i)
        float rsum = 0.0f;
        #pragma unroll
        for (int c = 0; c < 8; ++c) {
            float iw = fmaxf(fminf(rb.z, jx2[c]) - fmaxf(rb.x, jx1[c]), 0.0f);
            float ih = fmaxf(fminf(rb.w, jy2[c]) - fmaxf(rb.y, jy1[c]), 0.0f);
            float inter = iw * ih;
            float uniS = fmaf(inter, -CINV, ra.x + jaC[c]);  // union/C (<0)
            float rc; asm("rcp.approx.ftz.f32 %0, %1;" : "=f"(rc) : "f"(uniS));
            float t = inter * rc;                             // C * iou
            float w; asm("ex2.approx.ftz.f32 %0, %1;" : "=f"(w) : "f"(t));
            float w1 = w - 1.0f;                              // 0 when no overlap
            if (diag) w1 = (cg * 8 + c > ir) ? w1 : 0.0f;     // strict upper
            cacc[c] = fmaf(w1, ra.y, cacc[c]);
            rsum    = fmaf(w1, js[c], rsum);
        }
        red[ir * 17 + cg] = rsum;
    }
    __syncthreads();

    // ---- row sums: 16 cg partials, fixed order ----
    float rowsum = 0.0f;
    if (tid < TILE) {
        rowsum = red[tid * 17 + 0];
        #pragma unroll
        for (int k = 1; k < 16; ++k)
            rowsum = __fadd_rn(rowsum, red[tid * 17 + k]);
    }
    __syncthreads();

    // ---- col sums: scatter cacc, reduce 16 rg partials ----
    #pragma unroll
    for (int c = 0; c < 8; ++c)
        red[(cg * 8 + c) * 17 + rg] = cacc[c];
    __syncthreads();

    float colsum = 0.0f;
    if (tid < TILE) {
        colsum = red[tid * 17 + 0];
        #pragma unroll
        for (int k = 1; k < 16; ++k)
            colsum = __fadd_rn(colsum, red[tid * 17 + k]);
    }

    // ---- store partials ----
    if (tid < TILE) {
        if (diag) {
            const float E2M1 = -0.86466471676338730f;   // exp(-2) - 1 self term
            float v = __fadd_rn(__fadd_rn(rowsum, colsum), E2M1 * sasI[tid].y);
            prow[ibase + tid] = v;
        } else {
            prow[ibase + tid] = rowsum;
            pcol[jbase + tid] = colsum;
        }
    }
}

// ---------------------------------------------------------------------------
// Kernel 2a: stage A reduce — 64 slots -> 8 groups. 256 CTAs x 256 threads.
// ---------------------------------------------------------------------------
__global__ __launch_bounds__(256)
void reduceA_kernel()
{
    const int g     = blockIdx.x & 7;
    const int chunk = blockIdx.x >> 3;
    const int idx   = chunk * 256 + threadIdx.x;

    float4 a = reinterpret_cast<const float4*>(g_part2[g * 8 + 0])[idx];
    #pragma unroll
    for (int s = 1; s < 8; ++s) {
        float4 v = reinterpret_cast<const float4*>(g_part2[g * 8 + s])[idx];
        a.x = __fadd_rn(a.x, v.x); a.y = __fadd_rn(a.y, v.y);
        a.z = __fadd_rn(a.z, v.z); a.w = __fadd_rn(a.w, v.w);
    }
    reinterpret_cast<float4*>(g_stage[g])[idx] = a;
}

// ---------------------------------------------------------------------------
// Kernel 2b: stage B reduce — 8 groups -> g_adj (+ S_b), + per-CTA max.
// ---------------------------------------------------------------------------
__global__ __launch_bounds__(256)
void reduceB_kernel()
{
    const int idx = blockIdx.x * 256 + threadIdx.x;
    const int b   = blockIdx.x >> 3;
    const float S = g_S[b];

    float4 a = reinterpret_cast<const float4*>(g_stage[0])[idx];
    #pragma unroll
    for (int s = 1; s < 8; ++s) {
        float4 v = reinterpret_cast<const float4*>(g_stage[s])[idx];
        a.x = __fadd_rn(a.x, v.x); a.y = __fadd_rn(a.y, v.y);
        a.z = __fadd_rn(a.z, v.z); a.w = __fadd_rn(a.w, v.w);
    }
    a.x = __fadd_rn(a.x, S); a.y = __fadd_rn(a.y, S);
    a.z = __fadd_rn(a.z, S); a.w = __fadd_rn(a.w, S);
    reinterpret_cast<float4*>(g_adj)[idx] = a;

    __shared__ float smax[8];
    float m = fmaxf(fmaxf(a.x, a.y), fmaxf(a.z, a.w));
    #pragma unroll
    for (int o = 16; o; o >>= 1) m = fmaxf(m, __shfl_xor_sync(0xffffffffu, m, o));
    if ((threadIdx.x & 31) == 0) smax[threadIdx.x >> 5] = m;
    __syncthreads();
    if (threadIdx.x == 0) {
        float mm = smax[0];
        #pragma unroll
        for (int w = 1; w < 8; ++w) mm = fmaxf(mm, smax[w]);
        g_pmax[blockIdx.x] = mm;
    }
}

// ---------------------------------------------------------------------------
// Kernel 3: per-batch softmax + weighted average. 4 CTAs x 1024 threads.
// ---------------------------------------------------------------------------
__global__ __launch_bounds__(1024)
void softfinal_kernel(float* __restrict__ out)
{
    const int b = blockIdx.x;
    const int t = threadIdx.x;

    float m = g_pmax[b * 8 + 0];
    #pragma unroll
    for (int k = 1; k < 8; ++k) m = fmaxf(m, g_pmax[b * 8 + k]);

    float se = 0.f, sx1 = 0.f, sy1 = 0.f, sx2 = 0.f, sy2 = 0.f;
    #pragma unroll
    for (int h = 0; h < 2; ++h) {
        int idx = b * 2048 + h * 1024 + t;
        float4 ad = reinterpret_cast<const float4*>(g_adj)[idx];
        float e0 = __expf(ad.x - m);
        float e1 = __expf(ad.y - m);
        float e2 = __expf(ad.z - m);
        float e3 = __expf(ad.w - m);
        float4 b0 = g_sbox[idx * 4 + 0];
        float4 b1 = g_sbox[idx * 4 + 1];
        float4 b2 = g_sbox[idx * 4 + 2];
        float4 b3 = g_sbox[idx * 4 + 3];
        se  += ((e0 + e1) + (e2 + e3));
        sx1 = fmaf(e0, b0.x, fmaf(e1, b1.x, fmaf(e2, b2.x, fmaf(e3, b3.x, sx1))));
        sy1 = fmaf(e0, b0.y, fmaf(e1, b1.y, fmaf(e2, b2.y, fmaf(e3, b3.y, sy1))));
        sx2 = fmaf(e0, b0.z, fmaf(e1, b1.z, fmaf(e2, b2.z, fmaf(e3, b3.z, sx2))));
        sy2 = fmaf(e0, b0.w, fmaf(e1, b1.w, fmaf(e2, b2.w, fmaf(e3, b3.w, sy2))));
    }

    __shared__ float s5[5][32];
    #pragma unroll
    for (int o = 16; o; o >>= 1) {
        se  += __shfl_xor_sync(0xffffffffu, se,  o);
        sx1 += __shfl_xor_sync(0xffffffffu, sx1, o);
        sy1 += __shfl_xor_sync(0xffffffffu, sy1, o);
        sx2 += __shfl_xor_sync(0xffffffffu, sx2, o);
        sy2 += __shfl_xor_sync(0xffffffffu, sy2, o);
    }
    if ((t & 31) == 0) {
        int w = t >> 5;
        s5[0][w] = se; s5[1][w] = sx1; s5[2][w] = sy1; s5[3][w] = sx2; s5[4][w] = sy2;
    }
    __syncthreads();
    if (t == 0) {
        float a[5];
        #pragma unroll
        for (int q = 0; q < 5; ++q) {
            float acc = s5[q][0];
            #pragma unroll
            for (int w = 1; w < 32; ++w) acc = __fadd_rn(acc, s5[q][w]);
            a[q] = acc;
        }
        float inv = 1.0f / a[0];
        out[b * 4 + 0] = a[1] * inv;
        out[b * 4 + 1] = a[2] * inv;
        out[b * 4 + 2] = a[3] * inv;
        out[b * 4 + 3] = a[4] * inv;
    }
}

// ---------------------------------------------------------------------------
extern "C" void kernel_launch(void* const* d_in, const int* in_sizes, int n_in,
                              void* d_out, int out_size)
{
    const float* boxes  = (const float*)d_in[0];
    const float* scores = (const float*)d_in[1];
    if (n_in >= 2 && in_sizes[0] == BATCH * NBOX && in_sizes[1] == BATCH * NBOX * 4) {
        const float* tmp = boxes; boxes = scores; scores = tmp;
    }
    float* out = (float*)d_out;

    bucket_kernel<<<BATCH, 1024>>>(boxes, scores);
    symm_kernel<<<dim3(NPAIRS, BATCH), THREADS>>>();
    reduceA_kernel<<<256, 256>>>();
    reduceB_kernel<<<32, 256>>>();
    softfinal_kernel<<<BATCH, 1024>>>(out);
}